// round 13
// baseline (speedup 1.0000x reference)
#include <cuda_runtime.h>
#include <cuda_fp16.h>
#include <cstdint>

#define SEQ 256
#define B_  32
#define TILE 4096   // 64*64 floats

// LAYOUT L4 (verified R10/R12): tile (b,t) at (t*32+b)*TILE; interior
// transposed: element (i,j) at offset j*64 + i.

__device__ float g_fv[32][64];
__device__ float g_bv[32][64];
__device__ float g_fo[32];
__device__ float g_bo[32];
__device__ float g_sc[32];
__device__ int   g_ct[32];
__device__ int   g_done;
__device__ float g_sink;

__device__ __forceinline__ void cp16(unsigned int dst, const float* src) {
    asm volatile("cp.async.cg.shared.global [%0], [%1], 16;\n" :: "r"(dst), "l"(src));
}
__device__ __forceinline__ void cp_commit() { asm volatile("cp.async.commit_group;\n" ::: "memory"); }
__device__ __forceinline__ void cp_wait2()  { asm volatile("cp.async.wait_group 2;\n" ::: "memory"); }

__device__ __forceinline__ int bf16_ok(unsigned h) {
    const float g = __uint_as_float(h << 16);
    return (h == 0u) || (g >= 1.f && g < 64.f && g == floorf(g));
}
__device__ __forceinline__ int decode_tgt(const unsigned* tu, int mode, int e) {
    int v;
    if      (mode == 0) v = (int)tu[2 * e];
    else if (mode == 1) v = (int)tu[e];
    else if (mode == 2) v = (int)((tu[e >> 1] >> ((e & 1) * 16)) & 0xFFFFu);
    else if (mode == 3) v = (int)((tu[e >> 2] >> ((e & 3) * 8)) & 0xFFu);
    else if (mode == 4) v = (int)__uint_as_float(tu[e]);
    else if (mode == 5) v = (int)__uint_as_float(((tu[e >> 1] >> ((e & 1) * 16)) & 0xFFFFu) << 16);
    else                v = (int)__hiloint2double(tu[2 * e + 1], tu[2 * e]);
    return v & 63;
}

// exp of 4 fp32 via two f16x2 ex2 (halves MUFU pressure vs fp32 EX2).
__device__ __forceinline__ float4 exp4f(float4 e) {
    const float L2E = 1.4426950408889634f;
    __half2 ha = h2exp2(__floats2half2_rn(e.x * L2E, e.y * L2E));
    __half2 hb = h2exp2(__floats2half2_rn(e.z * L2E, e.w * L2E));
    const float2 fa = __half22float2(ha);
    const float2 fb = __half22float2(hb);
    return make_float4(fa.x, fa.y, fb.x, fb.y);
}

// -------------------------------------------------------------------------
// One fused kernel, grid = 148 blocks:
//   blocks 0..63  : scan chains (b = blk>>1, dir = blk&1), as R12 + f16x2 exp
//   blocks 64..147: L2-warming helpers streaming tiles in the same
//                   distance-priority order the consumers need them
// Block 0 performs the final loss reduction after all 64 chains arrive.
// -------------------------------------------------------------------------
__global__ void __launch_bounds__(256) crf_fused(const float* __restrict__ emits,
                                                 const unsigned char* __restrict__ mask,
                                                 const unsigned* __restrict__ tu,
                                                 float* __restrict__ out)
{
    const int blk = blockIdx.x;
    const int tid = threadIdx.x;

    if (blk >= 64) {
        // ---------------- L2-warming helper ----------------
        float acc = 0.f;
        for (int w = blk - 64; w < 8160; w += 84) {
            const int dd = w >> 6, r = w & 63;
            if (dd == 127 && r >= 32) continue;     // t=128 covered once
            const int t = (r & 32) ? 255 - dd : 1 + dd;
            const int b = r & 31;
            const float4* src = (const float4*)(emits + (size_t)(t * B_ + b) * TILE);
            #pragma unroll
            for (int k = 0; k < 4; k++) {
                const float4 v = __ldcg(&src[k * 256 + tid]);
                acc += v.x + v.y + v.z + v.w;
            }
        }
        if (acc == 1.234567e-33f) g_sink = acc;     // keep loads alive
        return;
    }

    // ---------------- scan chain ----------------
    extern __shared__ float smem[];
    float* stage = smem;                    // 4 stages x 4096 floats
    float* sA    = smem + 4 * 4096;         // 64
    float* sMax  = sA + 64;                 // 8
    __shared__ unsigned char sM[256];
    __shared__ float sRed2[2];
    __shared__ float sv[8];
    __shared__ int   scnt[8];
    __shared__ double sAcc[8];
    __shared__ int   sCt2[8];

    const int b = blk >> 1, dir = blk & 1;
    const int sidx = tid & 15;
    const int oidx = tid >> 4;
    const int rb   = dir ? sidx : oidx;
    const int cc   = dir ? oidx : sidx;
    const int rdoff = ((cc ^ (rb & 7)) << 2);

    const unsigned int stage_u32 = (unsigned int)__cvta_generic_to_shared(stage);

    int cp_m[4];
    unsigned int cp_d[4];
    #pragma unroll
    for (int k = 0; k < 4; k++) {
        const int m = k * 256 + tid;
        const int row = m >> 4, c = m & 15;
        cp_m[k] = m;
        cp_d[k] = (unsigned int)((row * 64 + ((c ^ ((row >> 2) & 7)) << 2)) * 4);
    }

    sM[tid] = mask[b * SEQ + tid];

    const int nsteps = dir ? 128 : 127;

    #pragma unroll
    for (int s = 0; s < 3; s++) {
        const int t = dir ? 255 - s : 1 + s;
        const float* src = emits + (size_t)(t * B_ + b) * TILE;
        const unsigned int stg = stage_u32 + (unsigned int)(s & 3) * 16384u;
        #pragma unroll
        for (int k = 0; k < 4; k++) cp16(stg + cp_d[k], src + cp_m[k] * 4);
        cp_commit();
    }

    float m0 = 0.f;
    if (dir == 0) {
        float e0 = (tid < 64) ? emits[(size_t)b * TILE + tid * 64] : -1e30f;
        if (tid < 64) {
            float v = e0;
            #pragma unroll
            for (int o = 16; o; o >>= 1) v = fmaxf(v, __shfl_xor_sync(~0u, v, o));
            if ((tid & 31) == 0) sRed2[tid >> 5] = v;
        }
        __syncthreads();
        m0 = fmaxf(sRed2[0], sRed2[1]);
        if (tid < 64) sA[tid] = __expf(e0 - m0);
    } else {
        if (tid < 64) sA[tid] = 1.f;
    }

    int K = 0;
    for (int s = 0; s < nsteps; s++) {
        cp_wait2();
        __syncthreads();

        {
            const int sp = s + 3;
            if (sp < nsteps) {
                const int t = dir ? 255 - sp : 1 + sp;
                const float* src = emits + (size_t)(t * B_ + b) * TILE;
                const unsigned int stg = stage_u32 + (unsigned int)(sp & 3) * 16384u;
                #pragma unroll
                for (int k = 0; k < 4; k++) cp16(stg + cp_d[k], src + cp_m[k] * 4);
            }
            cp_commit();
        }

        const float* st = stage + (s & 3) * 4096;
        const float4 A4 = *(const float4*)&sA[sidx * 4];

        const float4 p0 = exp4f(*(const float4*)&st[(rb * 4 + 0) * 64 + rdoff]);
        const float4 p1 = exp4f(*(const float4*)&st[(rb * 4 + 1) * 64 + rdoff]);
        const float4 p2 = exp4f(*(const float4*)&st[(rb * 4 + 2) * 64 + rdoff]);
        const float4 p3 = exp4f(*(const float4*)&st[(rb * 4 + 3) * 64 + rdoff]);

        float4 acc;
        if (dir == 0) {
            acc.x = A4.x * p0.x + A4.y * p0.y + A4.z * p0.z + A4.w * p0.w;
            acc.y = A4.x * p1.x + A4.y * p1.y + A4.z * p1.z + A4.w * p1.w;
            acc.z = A4.x * p2.x + A4.y * p2.y + A4.z * p2.z + A4.w * p2.w;
            acc.w = A4.x * p3.x + A4.y * p3.y + A4.z * p3.z + A4.w * p3.w;
        } else {
            acc.x = A4.x * p0.x + A4.y * p1.x + A4.z * p2.x + A4.w * p3.x;
            acc.y = A4.x * p0.y + A4.y * p1.y + A4.z * p2.y + A4.w * p3.y;
            acc.z = A4.x * p0.z + A4.y * p1.z + A4.z * p2.z + A4.w * p3.z;
            acc.w = A4.x * p0.w + A4.y * p1.w + A4.z * p2.w + A4.w * p3.w;
        }

        #pragma unroll
        for (int o = 1; o <= 8; o <<= 1) {
            acc.x += __shfl_xor_sync(~0u, acc.x, o);
            acc.y += __shfl_xor_sync(~0u, acc.y, o);
            acc.z += __shfl_xor_sync(~0u, acc.z, o);
            acc.w += __shfl_xor_sync(~0u, acc.w, o);
        }

        const int t = dir ? 255 - s : 1 + s;
        const bool msk = sM[t] != 0;

        if ((s & 3) == 3) {
            float m = fmaxf(fmaxf(acc.x, acc.y), fmaxf(acc.z, acc.w));
            m = fmaxf(m, __shfl_xor_sync(~0u, m, 16));
            if ((tid & 31) == 0) sMax[tid >> 5] = m;
            __syncthreads();
            const float4 x0 = *(const float4*)&sMax[0];
            const float4 x1 = *(const float4*)&sMax[4];
            const float gm = fmaxf(fmaxf(fmaxf(x0.x, x0.y), fmaxf(x0.z, x0.w)),
                                   fmaxf(fmaxf(x1.x, x1.y), fmaxf(x1.z, x1.w)));
            if (msk) {
                const int kx = ((__float_as_int(gm) >> 23) & 0xFF) - 127;
                const float scale = __int_as_float((127 - kx) << 23);
                K += kx;
                acc.x *= scale; acc.y *= scale; acc.z *= scale; acc.w *= scale;
            }
        }

        if (msk && sidx == 0) *(float4*)&sA[oidx * 4] = acc;
    }

    __syncthreads();
    if (tid < 64) {
        if (dir == 0) g_fv[b][tid] = sA[tid];
        else          g_bv[b][tid] = sA[tid];
    }
    if (tid == 0) {
        const float off = (float)K * 0.6931471805599453f + (dir ? 0.f : m0);
        if (dir == 0) g_fo[b] = off; else g_bo[b] = off;
    }

    // ---- dir==0 epilogue: path score for batch b ----
    if (dir == 0) {
        const unsigned w  = tu[tid];
        const unsigned h0 = w & 0xFFFFu, h1 = w >> 16;
        const float    f  = __uint_as_float(w);
        int okA = (tid & 1) ? (w == 0u) : (w < 64u);
        int okB = (w < 64u);
        int okI = (h0 < 64u) && (h1 < 64u);
        int okE = ((w & 0xC0C0C0C0u) == 0u);
        int okC = (w == 0u) || (f >= 1.f && f < 64.f && f == floorf(f));
        int okF = bf16_ok(h0) && bf16_ok(h1);
        okA = __syncthreads_and(okA);
        okB = __syncthreads_and(okB);
        okI = __syncthreads_and(okI);
        okE = __syncthreads_and(okE);
        okC = __syncthreads_and(okC);
        okF = __syncthreads_and(okF);
        const int mode = okA ? 0 : okB ? 1 : okI ? 2 : okE ? 3 : okC ? 4 : okF ? 5 : 6;

        const int row = b * (SEQ + 1);
        const int i0 = decode_tgt(tu, mode, row + tid);
        const int i1 = decode_tgt(tu, mode, row + tid + 1);

        float v = 0.f; int c = 0;
        if (sM[tid]) {
            v = emits[(size_t)(tid * B_ + b) * TILE + i1 * 64 + i0];
            c = 1;
        }
        #pragma unroll
        for (int o = 16; o; o >>= 1) {
            v += __shfl_xor_sync(~0u, v, o);
            c += __shfl_xor_sync(~0u, c, o);
        }
        if ((tid & 31) == 0) { sv[tid >> 5] = v; scnt[tid >> 5] = c; }
        __syncthreads();
        if (tid == 0) {
            float tv = 0.f; int tc = 0;
            #pragma unroll
            for (int k = 0; k < 8; k++) { tv += sv[k]; tc += scnt[k]; }
            g_sc[b] = tv;
            g_ct[b] = tc;
        }
    }

    // ---- arrive; block 0 finishes the loss ----
    __threadfence();
    __syncthreads();
    if (tid == 0) atomicAdd(&g_done, 1);

    if (blk == 0) {
        if (tid == 0) {
            while (atomicAdd(&g_done, 0) < 64) __nanosleep(64);
            __threadfence();
        }
        __syncthreads();

        const int w = tid >> 5, l = tid & 31;
        double accd = 0.0; int ctd = 0;
        for (int bb = w; bb < 32; bb += 8) {
            float part = g_fv[bb][l] * g_bv[bb][l] + g_fv[bb][l + 32] * g_bv[bb][l + 32];
            #pragma unroll
            for (int o = 16; o; o >>= 1) part += __shfl_xor_sync(~0u, part, o);
            if (l == 0) {
                accd += (double)(logf(part) + g_fo[bb] + g_bo[bb]) - (double)g_sc[bb];
                ctd  += g_ct[bb];
            }
        }
        if (l == 0) { sAcc[w] = accd; sCt2[w] = ctd; }
        __syncthreads();
        if (tid == 0) {
            double s = 0.0; int c = 0;
            #pragma unroll
            for (int k = 0; k < 8; k++) { s += sAcc[k]; c += sCt2[k]; }
            out[0] = (float)(s / (double)c);
            __threadfence();
            g_done = 0;   // reset for next graph replay
        }
    }
}

extern "C" void kernel_launch(void* const* d_in, const int* in_sizes, int n_in,
                              void* d_out, int out_size)
{
    int ie = 0;
    for (int k = 1; k < n_in; k++) if (in_sizes[k] > in_sizes[ie]) ie = k;
    int im = -1, it = -1;
    for (int k = 0; k < n_in; k++) {
        if (k == ie) continue;
        if (in_sizes[k] == 8192 && im < 0) im = k; else it = k;
    }
    if (im < 0) { im = 2; }
    if (it < 0) { it = (im == 1) ? 2 : 1; }

    const float*         emits = (const float*)d_in[ie];
    const unsigned*      tg    = (const unsigned*)d_in[it];
    const unsigned char* mask  = (const unsigned char*)d_in[im];

    const int smem_bytes = 4 * 4096 * 4 + (64 + 8) * 4;   // 65824
    cudaFuncSetAttribute(crf_fused, cudaFuncAttributeMaxDynamicSharedMemorySize, smem_bytes);

    crf_fused<<<148, 256, smem_bytes>>>(emits, mask, tg, (float*)d_out);
}